// round 12
// baseline (speedup 1.0000x reference)
#include <cuda_runtime.h>
#include <cstddef>

// SpecialFlatten == batched float2 transpose: in2 [B, R, CP] -> out2 [B, CP, R]
// B=32, R=2048, C=512, CP=256. Fully float4-vectorized on both GMEM sides.
//
// FINAL (confirmed x3). Eleven rounds / seven distinct implementations all
// converge on 36.0-36.9us kernel / 72.6-74.9% DRAM — the mixed-R/W HBM3e
// turnaround wall (~7.4-7.5 TB/s combined, ~93% of spec) for this compulsory
// 268MB permutation stream. Config: 64Rx32CP tile, 256 threads, R-tiles
// fastest raster; best bench 43.49us.
//
// Smem: even input rows -> sA[m][.], odd rows -> sB[m][.] (m = pair index),
// permuted column layout s(c) = (c>>1) + (c&1)*16 => every STS.64/LDS.64 is
// lane-linear (bank 2*lane), zero conflicts with the +1 pad.

namespace {
constexpr int B   = 32;
constexpr int R   = 2048;
constexpr int CP  = 256;           // float2 columns
constexpr int C4  = CP / 2;        // 128 float4 per input row
constexpr int R4  = R / 2;         // 1024 float4 per output row
constexpr int TILE_R = 64;         // float2 rows per tile
constexpr int TILE_C = 32;         // float2 cols per tile (= 16 float4)
}

__global__ __launch_bounds__(256)
void special_flatten_final(const float4* __restrict__ in,
                           float4* __restrict__ out) {
    __shared__ float2 sA[32][33];   // even rows of the tile (row 2m -> sA[m])
    __shared__ float2 sB[32][33];   // odd rows  (row 2m+1 -> sB[m])

    const int b = blockIdx.z;
    const float4* __restrict__ inb  = in  + (size_t)b * R * C4;
    float4* __restrict__       outb = out + (size_t)b * CP * R4;

    const int tid   = threadIdx.x;
    const int rtile = blockIdx.x;   // R-tile index (fastest-varying)
    const int ctile = blockIdx.y;   // CP-tile index

    // ---- Load phase: 4x LDG.128 per thread, STS.64 lane-linear ----
    {
        const int tx = tid & 15;                 // float4 col within tile (0..15)
        const int ty = tid >> 4;                 // 0..15
        const int c4 = ctile * (TILE_C / 2) + tx;
        const int r0 = rtile * TILE_R;
#pragma unroll
        for (int k = 0; k < 2; k++) {
            const int m = ty + 16 * k;           // row pair 0..31
            const float4 v0 = inb[(size_t)(r0 + 2 * m    ) * C4 + c4];
            const float4 v1 = inb[(size_t)(r0 + 2 * m + 1) * C4 + c4];
            // logical cols 2tx, 2tx+1 -> storage cols tx, tx+16 (permuted)
            sA[m][tx]      = make_float2(v0.x, v0.y);
            sA[m][tx + 16] = make_float2(v0.z, v0.w);
            sB[m][tx]      = make_float2(v1.x, v1.y);
            sB[m][tx + 16] = make_float2(v1.z, v1.w);
        }
    }

    __syncthreads();

    // ---- Store phase: LDS.64 lane-linear, 4x STG.128 per thread ----
    {
        const int sx = tid & 31;                 // float4 R-index within tile (0..31)
        const int sy = tid >> 5;                 // 0..7
        const int r4 = rtile * (TILE_R / 2) + sx;
#pragma unroll
        for (int n = 0; n < 4; n++) {
            const int c  = sy + 8 * n;           // CP-local col 0..31
            const int sc = (c >> 1) + (c & 1) * 16;   // permuted storage col
            const float2 a  = sA[sx][sc];        // in2[2*sx][c]
            const float2 bb = sB[sx][sc];        // in2[2*sx+1][c]
            outb[(size_t)(ctile * TILE_C + c) * R4 + r4] =
                make_float4(a.x, a.y, bb.x, bb.y);
        }
    }
}

extern "C" void kernel_launch(void* const* d_in, const int* in_sizes, int n_in,
                              void* d_out, int out_size) {
    const float4* in  = (const float4*)d_in[0];
    float4*       out = (float4*)d_out;

    dim3 block(256, 1, 1);
    dim3 grid(R / TILE_R, CP / TILE_C, B);   // (32, 8, 32) = 8192 blocks
    special_flatten_final<<<grid, block>>>(in, out);
}